// round 12
// baseline (speedup 1.0000x reference)
#include <cuda_runtime.h>
#include <cstdint>

#define NC 5
#define NR 14
#define NPLANES 33          // 5 chem + 14 mu + 14 vu
#define NS 4                // pipeline stages
#define NTHREADS 128
#define UNIT 128            // elements per unit (1 per thread)
#define PLANE_BYTES (UNIT * 4)              // 512
#define STAGE_BYTES (NPLANES * PLANE_BYTES) // 16896
#define SMEM_DATA_OFF 1024
#define SMEM_TOTAL (SMEM_DATA_OFF + NS * STAGE_BYTES)  // 68608

__device__ __forceinline__ float fast_tanh(float x) {
    float r;
    asm("tanh.approx.f32 %0, %1;" : "=f"(r) : "f"(x));
    return r;
}

__device__ __forceinline__ void stcs1(float* p, float v) {
    asm("st.global.cs.f32 [%0], %1;" :: "l"(p), "f"(v) : "memory");
}

__device__ __forceinline__ uint32_t smem_u32(const void* p) {
    uint32_t a;
    asm("{ .reg .u64 t; cvta.to.shared.u64 t, %1; cvt.u32.u64 %0, t; }"
        : "=r"(a) : "l"(p));
    return a;
}

__device__ __forceinline__ void mbar_init(uint32_t addr, uint32_t count) {
    asm volatile("mbarrier.init.shared.b64 [%0], %1;"
                 :: "r"(addr), "r"(count) : "memory");
}

__device__ __forceinline__ void mbar_expect_tx(uint32_t addr, uint32_t bytes) {
    asm volatile("mbarrier.arrive.expect_tx.shared.b64 _, [%0], %1;"
                 :: "r"(addr), "r"(bytes) : "memory");
}

__device__ __forceinline__ void mbar_arrive(uint32_t addr) {
    asm volatile("mbarrier.arrive.shared.b64 _, [%0];"
                 :: "r"(addr) : "memory");
}

__device__ __forceinline__ void mbar_wait(uint32_t addr, uint32_t phase) {
    asm volatile(
        "{\n\t"
        ".reg .pred P;\n\t"
        "WL_%=:\n\t"
        "mbarrier.try_wait.parity.acquire.cta.shared::cta.b64 P, [%0], %1, 0x989680;\n\t"
        "@P bra.uni WD_%=;\n\t"
        "bra.uni WL_%=;\n\t"
        "WD_%=:\n\t"
        "}"
        :: "r"(addr), "r"(phase) : "memory");
}

__device__ __forceinline__ void bulk_g2s(uint32_t dst, const void* src,
                                         uint32_t bytes, uint32_t mbar) {
    asm volatile(
        "cp.async.bulk.shared::cluster.global.mbarrier::complete_tx::bytes "
        "[%0], [%1], %2, [%3];"
        :: "r"(dst), "l"(src), "r"(bytes), "r"(mbar) : "memory");
}

extern __shared__ char dsm[];

__global__ __launch_bounds__(NTHREADS, 3) void rnn_tma_kernel(
    const float* __restrict__ chem,   // [C, MN]
    const float* __restrict__ mu,     // [R, MN]
    const float* __restrict__ vu,     // [R, MN]
    const float* __restrict__ Q,      // [C, 2R]
    const float* __restrict__ Ks,     // [C, C]
    const float* __restrict__ v,      // [1, C]
    const float* __restrict__ y,      // [C]
    const float* __restrict__ z,      // [C]
    const int*   __restrict__ tptr,   // scalar time_index
    float* __restrict__ out,          // [MN]
    int MN)                           // 2048*1024
{
    __shared__ float sA[NR], sB[NR], sBp[NR];
    __shared__ float sa[NC], sw[NC], sK[NC * NC];

    const uint32_t sbase = smem_u32(dsm);
    const int tid = threadIdx.x;

    // mbar layout in dynamic smem: full[s] @ 8s, empty[s] @ 256+8s
    if (tid == 0) {
        float invt = 1.0f / (float)(*tptr);
        float wreg[NC];
        #pragma unroll
        for (int c = 0; c < NC; ++c) {
            float vc = v[c];
            sa[c] = vc * y[c];
            wreg[c] = vc * z[c];
            sw[c] = wreg[c];
        }
        #pragma unroll
        for (int c = 0; c < NC; ++c)
            #pragma unroll
            for (int d = 0; d < NC; ++d)
                sK[c * NC + d] = Ks[c * NC + d];
        #pragma unroll
        for (int r = 0; r < NR; ++r) {
            float A = 0.0f, B = 0.0f;
            #pragma unroll
            for (int c = 0; c < NC; ++c) {
                A = fmaf(wreg[c], Q[c * (2 * NR) + r], A);
                B = fmaf(wreg[c], Q[c * (2 * NR) + NR + r], B);
            }
            sA[r] = A;
            sB[r] = B;
            sBp[r] = B * invt;
        }
        #pragma unroll
        for (int s = 0; s < NS; ++s) {
            mbar_init(sbase + 8u * s, 1);            // full: 1 expect_tx arrive
            mbar_init(sbase + 256u + 8u * s, NTHREADS); // empty: all threads
        }
    }
    __syncthreads();

    const int nUnits = MN / UNIT;
    const int grid = gridDim.x;
    const int bid = blockIdx.x;

    // Producer cursor (tid 0 only): phase starts at 1 so first empty-waits
    // pass immediately. Consumer cursor: phase 0.
    int pstage = 0, pphase = 1;
    int cstage = 0, cphase = 0;

    // Issues the 33 bulk copies for unit u into stage.
    auto fill = [&](int u, int stage) {
        const uint32_t mbar = sbase + 8u * stage;
        const uint32_t dst = sbase + SMEM_DATA_OFF + (uint32_t)stage * STAGE_BYTES;
        mbar_expect_tx(mbar, STAGE_BYTES);
        const size_t off = (size_t)u * UNIT;
        #pragma unroll
        for (int c = 0; c < NC; ++c)
            bulk_g2s(dst + c * PLANE_BYTES,
                     chem + (size_t)c * MN + off, PLANE_BYTES, mbar);
        #pragma unroll
        for (int r = 0; r < NR; ++r)
            bulk_g2s(dst + (NC + r) * PLANE_BYTES,
                     mu + (size_t)r * MN + off, PLANE_BYTES, mbar);
        #pragma unroll
        for (int r = 0; r < NR; ++r)
            bulk_g2s(dst + (NC + NR + r) * PLANE_BYTES,
                     vu + (size_t)r * MN + off, PLANE_BYTES, mbar);
    };

    // Prologue: fill first NS-1 stages (all in range: grid*(NS-1) << nUnits).
    if (tid == 0) {
        #pragma unroll
        for (int k = 0; k < NS - 1; ++k) {
            int fu = bid + k * grid;
            if (fu < nUnits) {
                mbar_wait(sbase + 256u + 8u * pstage, pphase); // passes
                fill(fu, pstage);
            }
            if (++pstage == NS) { pstage = 0; pphase ^= 1; }
        }
    }

    int n = 0;
    for (int u = bid; u < nUnits; u += grid, ++n) {
        if (tid == 0) {
            int fu = bid + (n + NS - 1) * grid;
            if (fu < nUnits) {
                mbar_wait(sbase + 256u + 8u * pstage, pphase);
                fill(fu, pstage);
            }
            if (++pstage == NS) { pstage = 0; pphase ^= 1; }
        }

        mbar_wait(sbase + 8u * cstage, cphase);
        const float* st = (const float*)(dsm + SMEM_DATA_OFF
                                         + (size_t)cstage * STAGE_BYTES);

        // chem part
        float x[NC];
        #pragma unroll
        for (int c = 0; c < NC; ++c)
            x[c] = st[c * UNIT + tid];

        float h = 0.0f;
        #pragma unroll
        for (int c = 0; c < NC; ++c) {
            float tc = 0.0f;
            #pragma unroll
            for (int d = 0; d < NC; ++d)
                tc = fmaf(sK[c * NC + d], x[d], tc);
            h = fmaf(sa[c], x[c], fmaf(sw[c], fast_tanh(tc), h));
        }

        // rule part: h += m*(A - B*m) + B'*u
        #pragma unroll
        for (int r = 0; r < NR; ++r) {
            float m  = st[(NC + r) * UNIT + tid];
            float uu = st[(NC + NR + r) * UNIT + tid];
            h = fmaf(m, fmaf(-sB[r], m, sA[r]), fmaf(sBp[r], uu, h));
        }

        stcs1(out + (size_t)u * UNIT + tid, h);

        mbar_arrive(sbase + 256u + 8u * cstage);   // release this stage
        if (++cstage == NS) { cstage = 0; cphase ^= 1; }
    }
}

extern "C" void kernel_launch(void* const* d_in, const int* in_sizes, int n_in,
                              void* d_out, int out_size) {
    const float* chem = (const float*)d_in[0];
    const float* mu   = (const float*)d_in[1];
    const float* vu   = (const float*)d_in[2];
    const float* Q    = (const float*)d_in[3];
    const float* Ks   = (const float*)d_in[4];
    const float* v    = (const float*)d_in[5];
    const float* y    = (const float*)d_in[6];
    const float* z    = (const float*)d_in[7];
    const int*   t    = (const int*)d_in[8];
    float* out = (float*)d_out;

    static bool attr_done = false;
    if (!attr_done) {
        cudaFuncSetAttribute(rnn_tma_kernel,
                             cudaFuncAttributeMaxDynamicSharedMemorySize,
                             SMEM_TOTAL);
        attr_done = true;
    }

    int MN = out_size;          // 2048*1024
    int blocks = 152 * 3;       // 3 CTAs/SM persistent

    rnn_tma_kernel<<<blocks, NTHREADS, SMEM_TOTAL>>>(
        chem, mu, vu, Q, Ks, v, y, z, t, out, MN);
}

// round 13
// speedup vs baseline: 1.1553x; 1.1553x over previous
#include <cuda_runtime.h>

#define NC 5
#define NR 14
#define NG 7   // rule groups of 2 rules each

__device__ unsigned int g_unit_ctr;

__global__ void reset_ctr_kernel(unsigned int v) {
    g_unit_ctr = v;
}

__device__ __forceinline__ float fast_tanh(float x) {
    float r;
    asm("tanh.approx.f32 %0, %1;" : "=f"(r) : "f"(x));
    return r;
}

__device__ __forceinline__ float4 ldcs4(const float4* p) {
    float4 r;
    asm("ld.global.cs.v4.f32 {%0,%1,%2,%3}, [%4];"
        : "=f"(r.x), "=f"(r.y), "=f"(r.z), "=f"(r.w) : "l"(p));
    return r;
}

__device__ __forceinline__ void stcs4(float4* p, float4 v) {
    asm("st.global.cs.v4.f32 [%0], {%1,%2,%3,%4};"
        :: "l"(p), "f"(v.x), "f"(v.y), "f"(v.z), "f"(v.w) : "memory");
}

__global__ __launch_bounds__(256, 4) void rnn_fused_kernel(
    const float* __restrict__ chem,   // [C, M*N]
    const float* __restrict__ mu,     // [R, M*N]
    const float* __restrict__ vu,     // [R, M*N]
    const float* __restrict__ Q,      // [C, 2R]
    const float* __restrict__ Ks,     // [C, C]
    const float* __restrict__ v,      // [1, C]
    const float* __restrict__ y,      // [C]
    const float* __restrict__ z,      // [C]
    const int*   __restrict__ tptr,   // scalar time_index
    float* __restrict__ out,          // [M*N]
    int quads)                        // M*N / 4 (multiple of 32)
{
    __shared__ float sA[NR], sB[NR], sBp[NR];
    __shared__ float sa[NC], sw[NC], sK[NC * NC];

    if (threadIdx.x == 0) {
        float invt = 1.0f / (float)(*tptr);
        float wreg[NC];
        #pragma unroll
        for (int c = 0; c < NC; ++c) {
            float vc = v[c];
            sa[c] = vc * y[c];
            wreg[c] = vc * z[c];
            sw[c] = wreg[c];
        }
        #pragma unroll
        for (int c = 0; c < NC; ++c)
            #pragma unroll
            for (int d = 0; d < NC; ++d)
                sK[c * NC + d] = Ks[c * NC + d];
        #pragma unroll
        for (int r = 0; r < NR; ++r) {
            float A = 0.0f, B = 0.0f;
            #pragma unroll
            for (int c = 0; c < NC; ++c) {
                A = fmaf(wreg[c], Q[c * (2 * NR) + r], A);
                B = fmaf(wreg[c], Q[c * (2 * NR) + NR + r], B);
            }
            sA[r] = A;
            sB[r] = B;
            sBp[r] = B * invt;
        }
    }
    __syncthreads();   // only barrier in the kernel; warps free-run after.

    const float4* ch4 = (const float4*)chem;
    const float4* mu4 = (const float4*)mu;
    const float4* vu4 = (const float4*)vu;
    float4* out4 = (float4*)out;

    const int lane = threadIdx.x & 31;
    const int num_units = quads >> 5;            // 32-quad units per warp
    int unit = blockIdx.x * (blockDim.x >> 5) + (threadIdx.x >> 5);

    while (unit < num_units) {
        // Steal next unit now (lane 0); broadcast AFTER the body so the
        // ATOMG round-trip (~318 cyc) is hidden behind ~2500 cyc of work.
        int next_u;
        if (lane == 0)
            next_u = (int)atomicAdd(&g_unit_ctr, 1u);

        const int i = unit * 32 + lane;

        // ---- R6 body, unchanged ----
        // (1) Issue ALL chem loads first; consumed last (epilogue).
        float4 cv[NC];
        #pragma unroll
        for (int c = 0; c < NC; ++c)
            cv[c] = ldcs4(&ch4[c * quads + i]);

        // (2) Rule loop, explicit double-buffered prefetch, 2 rules/group.
        float4 mb[2][2], ub[2][2];
        mb[0][0] = ldcs4(&mu4[0 * quads + i]);
        mb[0][1] = ldcs4(&mu4[1 * quads + i]);
        ub[0][0] = ldcs4(&vu4[0 * quads + i]);
        ub[0][1] = ldcs4(&vu4[1 * quads + i]);

        float h[4] = {0.f, 0.f, 0.f, 0.f};

        #pragma unroll
        for (int g = 0; g < NG; ++g) {
            const int cb = g & 1, nb = cb ^ 1;
            if (g < NG - 1) {
                const int r = 2 * (g + 1);
                mb[nb][0] = ldcs4(&mu4[(r    ) * quads + i]);
                mb[nb][1] = ldcs4(&mu4[(r + 1) * quads + i]);
                ub[nb][0] = ldcs4(&vu4[(r    ) * quads + i]);
                ub[nb][1] = ldcs4(&vu4[(r + 1) * quads + i]);
            }
            #pragma unroll
            for (int j = 0; j < 2; ++j) {
                const int r = 2 * g + j;
                const float Ar = sA[r], Br = sB[r], Bp = sBp[r];
                const float4 m = mb[cb][j];
                const float4 u = ub[cb][j];
                const float mm[4] = {m.x, m.y, m.z, m.w};
                const float uu[4] = {u.x, u.y, u.z, u.w};
                #pragma unroll
                for (int k = 0; k < 4; ++k)
                    h[k] = fmaf(mm[k], fmaf(-Br, mm[k], Ar),
                                 fmaf(Bp, uu[k], h[k]));
            }
        }

        // (3) Chemical epilogue: cv[] arrived long ago.
        const float x0[NC] = {cv[0].x, cv[1].x, cv[2].x, cv[3].x, cv[4].x};
        const float x1[NC] = {cv[0].y, cv[1].y, cv[2].y, cv[3].y, cv[4].y};
        const float x2[NC] = {cv[0].z, cv[1].z, cv[2].z, cv[3].z, cv[4].z};
        const float x3[NC] = {cv[0].w, cv[1].w, cv[2].w, cv[3].w, cv[4].w};

        #pragma unroll
        for (int c = 0; c < NC; ++c) {
            float t0 = 0.f, t1 = 0.f, t2 = 0.f, t3 = 0.f;
            #pragma unroll
            for (int d = 0; d < NC; ++d) {
                const float kcd = sK[c * NC + d];
                t0 = fmaf(kcd, x0[d], t0);
                t1 = fmaf(kcd, x1[d], t1);
                t2 = fmaf(kcd, x2[d], t2);
                t3 = fmaf(kcd, x3[d], t3);
            }
            const float ac = sa[c], wc = sw[c];
            h[0] = fmaf(ac, x0[c], fmaf(wc, fast_tanh(t0), h[0]));
            h[1] = fmaf(ac, x1[c], fmaf(wc, fast_tanh(t1), h[1]));
            h[2] = fmaf(ac, x2[c], fmaf(wc, fast_tanh(t2), h[2]));
            h[3] = fmaf(ac, x3[c], fmaf(wc, fast_tanh(t3), h[3]));
        }

        stcs4(&out4[i], make_float4(h[0], h[1], h[2], h[3]));

        // Warp-private broadcast; no CTA barrier, warps stay decoupled.
        unit = __shfl_sync(0xffffffffu, next_u, 0);
    }
}

extern "C" void kernel_launch(void* const* d_in, const int* in_sizes, int n_in,
                              void* d_out, int out_size) {
    const float* chem = (const float*)d_in[0];
    const float* mu   = (const float*)d_in[1];
    const float* vu   = (const float*)d_in[2];
    const float* Q    = (const float*)d_in[3];
    const float* Ks   = (const float*)d_in[4];
    const float* v    = (const float*)d_in[5];
    const float* y    = (const float*)d_in[6];
    const float* z    = (const float*)d_in[7];
    const int*   t    = (const int*)d_in[8];
    float* out = (float*)d_out;

    int quads = out_size / 4;   // M*N / 4 = 524288
    int threads = 256;
    int blocks = 152 * 4;       // persistent: 152 SMs x 4 CTAs/SM

    // Units [0, total_warps) are pre-assigned; counter starts above them.
    unsigned int total_warps = (unsigned int)blocks * (threads / 32);
    reset_ctr_kernel<<<1, 1>>>(total_warps);
    rnn_fused_kernel<<<blocks, threads>>>(chem, mu, vu, Q, Ks, v, y, z, t,
                                          out, quads);
}

// round 14
// speedup vs baseline: 1.2600x; 1.0907x over previous
#include <cuda_runtime.h>

#define NC 5
#define NR 14
#define NG 7   // rule groups of 2 rules each

__device__ __forceinline__ float fast_tanh(float x) {
    float r;
    asm("tanh.approx.f32 %0, %1;" : "=f"(r) : "f"(x));
    return r;
}

__device__ __forceinline__ float4 ldcs4(const float4* p) {
    float4 r;
    asm("ld.global.cs.v4.f32 {%0,%1,%2,%3}, [%4];"
        : "=f"(r.x), "=f"(r.y), "=f"(r.z), "=f"(r.w) : "l"(p));
    return r;
}

__device__ __forceinline__ void stcs4(float4* p, float4 v) {
    asm("st.global.cs.v4.f32 [%0], {%1,%2,%3,%4};"
        :: "l"(p), "f"(v.x), "f"(v.y), "f"(v.z), "f"(v.w) : "memory");
}

__global__ __launch_bounds__(256, 4) void rnn_fused_kernel(
    const float* __restrict__ chem,   // [C, M*N]
    const float* __restrict__ mu,     // [R, M*N]
    const float* __restrict__ vu,     // [R, M*N]
    const float* __restrict__ Q,      // [C, 2R]
    const float* __restrict__ Ks,     // [C, C]
    const float* __restrict__ v,      // [1, C]
    const float* __restrict__ y,      // [C]
    const float* __restrict__ z,      // [C]
    const int*   __restrict__ tptr,   // scalar time_index
    float* __restrict__ out,          // [M*N]
    int quads)                        // M*N / 4
{
    __shared__ float sA[NR], sB[NR], sBp[NR];
    __shared__ float sa[NC], sw[NC], sK[NC * NC];

    if (threadIdx.x == 0) {
        float invt = 1.0f / (float)(*tptr);
        float wreg[NC];
        #pragma unroll
        for (int c = 0; c < NC; ++c) {
            float vc = v[c];
            sa[c] = vc * y[c];
            wreg[c] = vc * z[c];
            sw[c] = wreg[c];
        }
        #pragma unroll
        for (int c = 0; c < NC; ++c)
            #pragma unroll
            for (int d = 0; d < NC; ++d)
                sK[c * NC + d] = Ks[c * NC + d];
        #pragma unroll
        for (int r = 0; r < NR; ++r) {
            float A = 0.0f, B = 0.0f;
            #pragma unroll
            for (int c = 0; c < NC; ++c) {
                A = fmaf(wreg[c], Q[c * (2 * NR) + r], A);
                B = fmaf(wreg[c], Q[c * (2 * NR) + NR + r], B);
            }
            sA[r] = A;
            sB[r] = B;
            sBp[r] = B * invt;
        }
    }
    __syncthreads();

    const float4* ch4 = (const float4*)chem;
    const float4* mu4 = (const float4*)mu;
    const float4* vu4 = (const float4*)vu;
    float4* out4 = (float4*)out;

    const int stride = gridDim.x * blockDim.x;

    for (int i = blockIdx.x * blockDim.x + threadIdx.x; i < quads;
         i += stride) {

        // (1) Issue ALL chem loads now; consumed last -> latency fully hidden
        //     behind the rule pipeline below.
        float4 cv[NC];
        #pragma unroll
        for (int c = 0; c < NC; ++c)
            cv[c] = ldcs4(&ch4[c * quads + i]);

        // (2) Rule loop, explicit double-buffered prefetch, 2 rules/group.
        float4 mb[2][2], ub[2][2];
        mb[0][0] = ldcs4(&mu4[0 * quads + i]);
        mb[0][1] = ldcs4(&mu4[1 * quads + i]);
        ub[0][0] = ldcs4(&vu4[0 * quads + i]);
        ub[0][1] = ldcs4(&vu4[1 * quads + i]);

        float h[4] = {0.f, 0.f, 0.f, 0.f};

        #pragma unroll
        for (int g = 0; g < NG; ++g) {
            const int cb = g & 1, nb = cb ^ 1;
            if (g < NG - 1) {
                const int r = 2 * (g + 1);
                mb[nb][0] = ldcs4(&mu4[(r    ) * quads + i]);
                mb[nb][1] = ldcs4(&mu4[(r + 1) * quads + i]);
                ub[nb][0] = ldcs4(&vu4[(r    ) * quads + i]);
                ub[nb][1] = ldcs4(&vu4[(r + 1) * quads + i]);
            }
            #pragma unroll
            for (int j = 0; j < 2; ++j) {
                const int r = 2 * g + j;
                const float Ar = sA[r], Br = sB[r], Bp = sBp[r];
                const float4 m = mb[cb][j];
                const float4 u = ub[cb][j];
                const float mm[4] = {m.x, m.y, m.z, m.w};
                const float uu[4] = {u.x, u.y, u.z, u.w};
                #pragma unroll
                for (int k = 0; k < 4; ++k)
                    h[k] = fmaf(mm[k], fmaf(-Br, mm[k], Ar),
                                 fmaf(Bp, uu[k], h[k]));
            }
        }

        // (3) Chemical part: cv[] arrived long ago.
        //     h += a_c * chem_c + w_c * tanh(K @ chem)
        const float x0[NC] = {cv[0].x, cv[1].x, cv[2].x, cv[3].x, cv[4].x};
        const float x1[NC] = {cv[0].y, cv[1].y, cv[2].y, cv[3].y, cv[4].y};
        const float x2[NC] = {cv[0].z, cv[1].z, cv[2].z, cv[3].z, cv[4].z};
        const float x3[NC] = {cv[0].w, cv[1].w, cv[2].w, cv[3].w, cv[4].w};

        #pragma unroll
        for (int c = 0; c < NC; ++c) {
            float t0 = 0.f, t1 = 0.f, t2 = 0.f, t3 = 0.f;
            #pragma unroll
            for (int d = 0; d < NC; ++d) {
                const float kcd = sK[c * NC + d];
                t0 = fmaf(kcd, x0[d], t0);
                t1 = fmaf(kcd, x1[d], t1);
                t2 = fmaf(kcd, x2[d], t2);
                t3 = fmaf(kcd, x3[d], t3);
            }
            const float ac = sa[c], wc = sw[c];
            h[0] = fmaf(ac, x0[c], fmaf(wc, fast_tanh(t0), h[0]));
            h[1] = fmaf(ac, x1[c], fmaf(wc, fast_tanh(t1), h[1]));
            h[2] = fmaf(ac, x2[c], fmaf(wc, fast_tanh(t2), h[2]));
            h[3] = fmaf(ac, x3[c], fmaf(wc, fast_tanh(t3), h[3]));
        }

        stcs4(&out4[i], make_float4(h[0], h[1], h[2], h[3]));
    }
}

extern "C" void kernel_launch(void* const* d_in, const int* in_sizes, int n_in,
                              void* d_out, int out_size) {
    const float* chem = (const float*)d_in[0];
    const float* mu   = (const float*)d_in[1];
    const float* vu   = (const float*)d_in[2];
    const float* Q    = (const float*)d_in[3];
    const float* Ks   = (const float*)d_in[4];
    const float* v    = (const float*)d_in[5];
    const float* y    = (const float*)d_in[6];
    const float* z    = (const float*)d_in[7];
    const int*   t    = (const int*)d_in[8];
    float* out = (float*)d_out;

    int quads = out_size / 4;   // M*N / 4 = 524288
    int threads = 256;
    int blocks = (quads + threads - 1) / threads;
    int persistent = 152 * 4;   // GB300: 152 SMs x 4 CTAs/SM
    if (blocks > persistent) blocks = persistent;

    rnn_fused_kernel<<<blocks, threads>>>(chem, mu, vu, Q, Ks, v, y, z, t,
                                          out, quads);
}